// round 10
// baseline (speedup 1.0000x reference)
#include <cuda_runtime.h>
#include <cuda_bf16.h>
#include <cstdint>

#define N_NEURONS 4096
#define N_EDGES   131072
#define VOCAB     8192
#define BB        8
#define TT        128
#define NB        (N_NEURONS*BB)
#define DECAYF    0.99f

#define RBLK   128
#define RTHR   1024
#define NWARPS 32
#define CAP    2048
#define MAXB   128

/* ------------------ static device scratch ------------------ */
__device__ float g_Xall[TT*NB];                  /* (t,n,b) */
__device__ float g_xs  [TT*NB];
__device__ float g_S   [N_NEURONS*16];           /* x: +0..7, y: +8..15 */
__device__ float g_A[NB];
__device__ int   g_perm [N_EDGES];
__device__ int   g_counts[N_NEURONS];
__device__ int   g_cursor[N_NEURONS];
__device__ int   g_rowptr[N_NEURONS+1];
__device__ __nv_bfloat16 g_Ahi[BB*TT*N_NEURONS];
__device__ __nv_bfloat16 g_Alo[BB*TT*N_NEURONS];
__device__ __nv_bfloat16 g_Whi[VOCAB*N_NEURONS];
__device__ __nv_bfloat16 g_Wlo[VOCAB*N_NEURONS];

/* distributed barrier: one flag per CTA, everyone polls all flags */
__device__ unsigned g_flags[RBLK];

__device__ __forceinline__ uint32_t smem_u32(const void* p) {
    uint32_t a;
    asm("{ .reg .u64 t; cvta.to.shared.u64 t, %1; cvt.u32.u64 %0, t; }" : "=r"(a) : "l"(p));
    return a;
}

/* ------------------ CSR preprocessing ------------------ */
__global__ void k_hist(const int* __restrict__ dst) {
    int e = blockIdx.x*blockDim.x + threadIdx.x;
    if (e < N_EDGES) atomicAdd(&g_counts[dst[e]], 1);
}
__global__ void k_scan() {
    __shared__ int sh[1024];
    int tid = threadIdx.x, base = tid*4;
    int v0 = g_counts[base+0], v1 = g_counts[base+1];
    int v2 = g_counts[base+2], v3 = g_counts[base+3];
    int s = v0+v1+v2+v3;
    sh[tid] = s; __syncthreads();
    for (int off = 1; off < 1024; off <<= 1) {
        int t = (tid >= off) ? sh[tid-off] : 0;
        __syncthreads(); sh[tid] += t; __syncthreads();
    }
    int excl = sh[tid] - s;
    g_rowptr[base+0] = excl; g_cursor[base+0] = excl; excl += v0;
    g_rowptr[base+1] = excl; g_cursor[base+1] = excl; excl += v1;
    g_rowptr[base+2] = excl; g_cursor[base+2] = excl; excl += v2;
    g_rowptr[base+3] = excl; g_cursor[base+3] = excl; excl += v3;
    if (tid == 1023) g_rowptr[N_NEURONS] = excl;
    g_counts[base+0]=0; g_counts[base+1]=0; g_counts[base+2]=0; g_counts[base+3]=0;
}
__global__ void k_scatter(const int* __restrict__ dst) {
    int e = blockIdx.x*blockDim.x + threadIdx.x;
    if (e < N_EDGES) { int p = atomicAdd(&g_cursor[dst[e]], 1); g_perm[p] = e; }
}

/* ------------------ W bf16 split ------------------ */
__global__ void k_convW(const float* __restrict__ W) {
    int i = blockIdx.x*blockDim.x + threadIdx.x;
    if (i >= VOCAB*N_NEURONS/4) return;
    float4 w = ((const float4*)W)[i];
    __nv_bfloat16 h[4], l[4];
    float v[4] = {w.x, w.y, w.z, w.w};
#pragma unroll
    for (int k = 0; k < 4; k++) {
        h[k] = __float2bfloat16_rn(v[k]);
        l[k] = __float2bfloat16_rn(v[k] - __bfloat162float(h[k]));
    }
    ((ushort4*)g_Whi)[i] = *(ushort4*)h;
    ((ushort4*)g_Wlo)[i] = *(ushort4*)l;
}

/* ------------------ grid barrier: one-hop distributed flags ---------------- */
/* Arrive: CTA's thread0 release-stores its flag (parallel across CTAs).
   Wait: every CTA's warp0 polls all 128 flags with RELAXED loads (parallel,
   one L2 round per poll), then one acquire fence upgrades the ordering.
   One hop: slowest store -> next poll round. No atomics, no aggregator. */
__device__ __forceinline__ void gbar(unsigned target) {
    __syncthreads();
    if (threadIdx.x < 32) {
        const int lane = threadIdx.x;
        if (lane == 0)
            asm volatile("st.global.release.gpu.u32 [%0], %1;"
                         :: "l"(&g_flags[blockIdx.x]), "r"(target) : "memory");
        unsigned v0, v1, v2, v3;
        bool ok;
        do {
            asm volatile("ld.global.relaxed.gpu.u32 %0, [%1];" : "=r"(v0) : "l"(&g_flags[lane     ]) : "memory");
            asm volatile("ld.global.relaxed.gpu.u32 %0, [%1];" : "=r"(v1) : "l"(&g_flags[lane + 32]) : "memory");
            asm volatile("ld.global.relaxed.gpu.u32 %0, [%1];" : "=r"(v2) : "l"(&g_flags[lane + 64]) : "memory");
            asm volatile("ld.global.relaxed.gpu.u32 %0, [%1];" : "=r"(v3) : "l"(&g_flags[lane + 96]) : "memory");
            ok = (v0 >= target) & (v1 >= target) & (v2 >= target) & (v3 >= target);
        } while (!__all_sync(0xffffffffu, ok));
        asm volatile("fence.acq_rel.gpu;" ::: "memory");
    }
    __syncthreads();
}

/* reset barrier state so graph replays start clean */
__global__ void k_rstbar() {
    if (threadIdx.x < RBLK) g_flags[threadIdx.x] = 0;
}

__device__ __forceinline__ void bfly4(float4& a) {
#pragma unroll
    for (int d = 2; d < 32; d <<= 1) {
        a.x += __shfl_xor_sync(0xffffffffu, a.x, d);
        a.y += __shfl_xor_sync(0xffffffffu, a.y, d);
        a.z += __shfl_xor_sync(0xffffffffu, a.z, d);
        a.w += __shfl_xor_sync(0xffffffffu, a.w, d);
    }
}

__global__ void __launch_bounds__(RTHR) k_recurrent(
        const int* __restrict__ idx, const float* __restrict__ Wemb,
        const int* __restrict__ srcA, const float* __restrict__ GxA,
        const float* __restrict__ GyA, const float* __restrict__ GsA,
        float* __restrict__ sig_out)
{
    __shared__ int   s_n[CAP];
    __shared__ float s_gs[CAP], s_gx[CAP], s_gy[CAP], s_sig[CAP];
    __shared__ int   s_wcnt[NWARPS], s_wbase[NWARPS+1];

    const int tid  = threadIdx.x;
    const int wid  = tid >> 5;
    const int lane = tid & 31;
    const int nrn  = blockIdx.x*NWARPS + wid;       /* 1 neuron per warp */
    const int h    = lane & 1;                      /* batch half */
    const int es   = lane >> 1;                     /* edge slot */
    const int gtid = blockIdx.x*RTHR + tid;
    unsigned bar = 0;

    /* embed */
    for (int id = gtid; id < TT*N_NEURONS; id += RBLK*RTHR) {
        int t = id >> 12, n = id & (N_NEURONS-1);
        float v[8];
#pragma unroll
        for (int bb = 0; bb < 8; bb++)
            v[bb] = Wemb[(size_t)idx[bb*TT + t]*N_NEURONS + n];
        float4* o = (float4*)&g_Xall[(size_t)id*8];
        o[0] = make_float4(v[0], v[1], v[2], v[3]);
        o[1] = make_float4(v[4], v[5], v[6], v[7]);
    }

    /* stage edges (padded to 32 per neuron) */
    const int grs = g_rowptr[nrn];
    const int cnt = g_rowptr[nrn+1] - grs;
    const int pc  = (cnt + 31) & ~31;
    if (lane == 0) s_wcnt[wid] = pc;
    __syncthreads();
    if (tid == 0) {
        int acc = 0;
        for (int w = 0; w < NWARPS; w++) { s_wbase[w] = acc; acc += s_wcnt[w]; }
        s_wbase[NWARPS] = acc;
    }
    __syncthreads();
    const int lb = s_wbase[wid];

    if (lane == 0) {
        int lbuf[MAXB];
        for (int j = 0; j < cnt; j++) lbuf[j] = g_perm[grs + j];
        for (int i = 1; i < cnt; i++) {
            int key = lbuf[i], j = i-1;
            while (j >= 0 && lbuf[j] > key) { lbuf[j+1] = lbuf[j]; j--; }
            lbuf[j+1] = key;
        }
        for (int j = 0; j < cnt; j++) s_n[lb + j] = lbuf[j];
    }
    __syncwarp();
    for (int j = lane; j < pc; j += 32) {
        int pos = lb + j;
        if (j < cnt) {
            int e = s_n[pos];
            g_perm[grs + j] = e;
            s_n[pos]  = srcA[e];
            s_gs[pos] = GsA[e];
            s_gx[pos] = GxA[e];
            s_gy[pos] = GyA[e];
        } else {
            s_n[pos] = 0; s_gs[pos] = 0.f; s_gx[pos] = 0.f; s_gy[pos] = 0.f;
        }
        s_sig[pos] = 0.0f;
    }
    gbar(++bar);

    /* y0 = X[:,0,:] */
    if (lane < 2)
        *(float4*)&g_S[nrn*16 + 8 + h*4] = *(const float4*)&g_Xall[nrn*8 + h*4];
    gbar(++bar);

    for (int t = 0; t < TT; t++) {
        const float* Xt = g_Xall + (size_t)t*NB;
        for (int layer = 0; layer < 2; layer++) {
            const float* xbase = (layer == 0) ? Xt : g_S;
            const int    xstr  = (layer == 0) ? 8 : 16;
            /* pass1: A[n] = sum x[src]*sigma(old) ; sigma hebbian update */
            {
                float4 xn4 = *(const float4*)(xbase + (size_t)nrn*xstr + h*4);
                float4 acc = make_float4(0.f, 0.f, 0.f, 0.f);
                for (int j0 = 0; j0 < pc; j0 += 16) {
                    int   slot = lb + j0 + es;
                    int   ns   = s_n[slot];
                    float sg   = s_sig[slot];
                    float4 xs4 = *(const float4*)(xbase + (size_t)ns*xstr + h*4);
                    float4 ys4 = *(const float4*)(&g_S[ns*16 + 8 + h*4]);
                    float p = ys4.x*xn4.x + ys4.y*xn4.y + ys4.z*xn4.z + ys4.w*xn4.w;
                    p += __shfl_xor_sync(0xffffffffu, p, 1);
                    acc.x += xs4.x*sg; acc.y += xs4.y*sg;
                    acc.z += xs4.z*sg; acc.w += xs4.w*sg;
                    if (h == 0)
                        s_sig[slot] = fmaf(p*0.125f, s_gs[slot], sg) * DECAYF;
                }
                bfly4(acc);
                if (lane < 2) *(float4*)&g_A[nrn*8 + h*4] = acc;
            }
            gbar(++bar);
            /* pass2: y[n] = sum relu(A[src])*Gy */
            {
                float4 acc = make_float4(0.f, 0.f, 0.f, 0.f);
                for (int j0 = 0; j0 < pc; j0 += 16) {
                    int   slot = lb + j0 + es;
                    int   ns   = s_n[slot];
                    float gy   = s_gy[slot];
                    float4 a4  = *(const float4*)(&g_A[ns*8 + h*4]);
                    a4.x = a4.x > 0.f ? a4.x : 0.f;  a4.y = a4.y > 0.f ? a4.y : 0.f;
                    a4.z = a4.z > 0.f ? a4.z : 0.f;  a4.w = a4.w > 0.f ? a4.w : 0.f;
                    acc.x += a4.x*gy; acc.y += a4.y*gy;
                    acc.z += a4.z*gy; acc.w += a4.w*gy;
                }
                bfly4(acc);
                if (lane < 2) *(float4*)&g_S[nrn*16 + 8 + h*4] = acc;
            }
            gbar(++bar);
            /* pass3: x[n] = relu(sum y[src]*Gx) */
            {
                float4 acc = make_float4(0.f, 0.f, 0.f, 0.f);
                for (int j0 = 0; j0 < pc; j0 += 16) {
                    int   slot = lb + j0 + es;
                    int   ns   = s_n[slot];
                    float gx   = s_gx[slot];
                    float4 y4  = *(const float4*)(&g_S[ns*16 + 8 + h*4]);
                    acc.x += y4.x*gx; acc.y += y4.y*gx;
                    acc.z += y4.z*gx; acc.w += y4.w*gx;
                }
                bfly4(acc);
                if (lane < 2) {
                    acc.x = acc.x > 0.f ? acc.x : 0.f;  acc.y = acc.y > 0.f ? acc.y : 0.f;
                    acc.z = acc.z > 0.f ? acc.z : 0.f;  acc.w = acc.w > 0.f ? acc.w : 0.f;
                    if (layer == 0) *(float4*)&g_S[nrn*16 + h*4] = acc;
                    else            *(float4*)&g_xs[(size_t)t*NB + nrn*8 + h*4] = acc;
                }
            }
            /* layer-1 pass3 output only feeds the final GEMM; next pass touches
               disjoint state -> that barrier is skipped. */
            if (layer == 0) gbar(++bar);
        }
    }

    if (sig_out)
        for (int j = lane; j < cnt; j += 32)
            sig_out[g_perm[grs + j]] = s_sig[lb + j];
}

/* ------------------ transpose + bf16 split of activations ------------------ */
__global__ void k_transpose() {
    int id = blockIdx.x*blockDim.x + threadIdx.x;
    if (id >= TT*N_NEURONS) return;
    int t = id >> 12, n = id & (N_NEURONS-1);
    const float4* p = (const float4*)&g_xs[(size_t)id*8];
    float4 v0 = p[0], v1 = p[1];
    float v[8] = {v0.x, v0.y, v0.z, v0.w, v1.x, v1.y, v1.z, v1.w};
#pragma unroll
    for (int bb = 0; bb < 8; bb++) {
        size_t o = (size_t)(bb*TT + t)*N_NEURONS + n;
        __nv_bfloat16 hh = __float2bfloat16_rn(v[bb]);
        g_Ahi[o] = hh;
        g_Alo[o] = __float2bfloat16_rn(v[bb] - __bfloat162float(hh));
    }
}

/* ------------------ mma.sync bf16 GEMM (split hi/lo, 3 segments) ----------- */
#define APITCH 40
#define STGB   (128*APITCH*2)
#define NSTG   3
#define SMEM_GEMM (2*NSTG*STGB)
#define NSTAGES_TOT 384

#define LDM4(r, a) asm volatile( \
    "ldmatrix.sync.aligned.m8n8.x4.shared.b16 {%0,%1,%2,%3}, [%4];" \
    : "=r"((r)[0]), "=r"((r)[1]), "=r"((r)[2]), "=r"((r)[3]) : "r"(a))

#define MMA16816(d, a, b0r, b1r) asm volatile( \
    "mma.sync.aligned.m16n8k16.row.col.f32.bf16.bf16.f32 " \
    "{%0,%1,%2,%3},{%4,%5,%6,%7},{%8,%9},{%0,%1,%2,%3};" \
    : "+f"((d)[0]), "+f"((d)[1]), "+f"((d)[2]), "+f"((d)[3]) \
    : "r"((a)[0]), "r"((a)[1]), "r"((a)[2]), "r"((a)[3]), "r"(b0r), "r"(b1r))

__global__ void __launch_bounds__(256) k_gemm_mma(const float* __restrict__ bias,
                                                  float* __restrict__ out)
{
    extern __shared__ char smem[];
    const uint32_t sA = smem_u32(smem);
    const uint32_t sB = sA + NSTG*STGB;
    const int tid  = threadIdx.x;
    const int wid  = tid >> 5;
    const int lane = tid & 31;
    const int wm = wid & 1, wn = wid >> 1;
    const int m0 = blockIdx.x * 128;
    const int n0 = blockIdx.y * 128;

    float acc[4][4][4];
#pragma unroll
    for (int i = 0; i < 4; i++)
#pragma unroll
        for (int j = 0; j < 4; j++)
#pragma unroll
            for (int k = 0; k < 4; k++) acc[i][j][k] = 0.0f;

    auto load_stage = [&](int gs, int slot) {
        int seg = gs >> 7;
        int k0  = (gs & 127) << 5;
        const __nv_bfloat16* Ap = (seg == 1) ? g_Alo : g_Ahi;
        const __nv_bfloat16* Bp = (seg == 2) ? g_Wlo : g_Whi;
#pragma unroll
        for (int i = tid; i < 512; i += 256) {
            int row = i >> 2, ch = i & 3;
            uint32_t da = sA + slot*STGB + (row*APITCH + ch*8)*2;
            const __nv_bfloat16* ga = Ap + (size_t)(m0 + row)*N_NEURONS + k0 + ch*8;
            asm volatile("cp.async.cg.shared.global [%0], [%1], 16;" :: "r"(da), "l"(ga) : "memory");
        }
#pragma unroll
        for (int i = tid; i < 512; i += 256) {
            int row = i >> 2, ch = i & 3;
            uint32_t db = sB + slot*STGB + (row*APITCH + ch*8)*2;
            const __nv_bfloat16* gb = Bp + (size_t)(n0 + row)*N_NEURONS + k0 + ch*8;
            asm volatile("cp.async.cg.shared.global [%0], [%1], 16;" :: "r"(db), "l"(gb) : "memory");
        }
        asm volatile("cp.async.commit_group;" ::: "memory");
    };

    load_stage(0, 0);
    load_stage(1, 1);

    for (int it = 0; it < NSTAGES_TOT; it++) {
        if (it + 2 < NSTAGES_TOT)
            asm volatile("cp.async.wait_group 1;" ::: "memory");
        else
            asm volatile("cp.async.wait_group 0;" ::: "memory");
        __syncthreads();
        if (it + 2 < NSTAGES_TOT)
            load_stage(it + 2, (it + 2) % NSTG);

        int slot = it % NSTG;
        uint32_t aB = sA + slot*STGB;
        uint32_t bB = sB + slot*STGB;
#pragma unroll
        for (int kk = 0; kk < 2; kk++) {
            uint32_t af[4][4], bf[2][4];
#pragma unroll
            for (int mi = 0; mi < 4; mi++) {
                uint32_t addr = aB + (uint32_t)(((wm*64 + mi*16 + (lane & 15))*APITCH
                                 + kk*16 + (lane >> 4)*8) * 2);
                LDM4(af[mi], addr);
            }
#pragma unroll
            for (int nh = 0; nh < 2; nh++) {
                int mat = lane >> 3;
                uint32_t addr = bB + (uint32_t)(((wn*32 + nh*16 + (lane & 7) + (mat >> 1)*8)*APITCH
                                 + kk*16 + (mat & 1)*8) * 2);
                LDM4(bf[nh], addr);
            }
#pragma unroll
            for (int mi = 0; mi < 4; mi++)
#pragma unroll
                for (int ni = 0; ni < 4; ni++)
                    MMA16816(acc[mi][ni], af[mi], bf[ni >> 1][(ni & 1)*2], bf[ni >> 1][(ni & 1)*2 + 1]);
        }
    }

    const int mb = m0 + wm*64;
    const int nb = n0 + wn*32;
#pragma unroll
    for (int ni = 0; ni < 4; ni++) {
        int c0 = nb + ni*8 + (lane & 3)*2;
        float bv0 = bias[c0], bv1 = bias[c0 + 1];
#pragma unroll
        for (int mi = 0; mi < 4; mi++) {
            int r0 = mb + mi*16 + (lane >> 2);
            float2 v0 = make_float2(acc[mi][ni][0] + bv0, acc[mi][ni][1] + bv1);
            float2 v1 = make_float2(acc[mi][ni][2] + bv0, acc[mi][ni][3] + bv1);
            *(float2*)&out[(size_t)r0*VOCAB + c0]       = v0;
            *(float2*)&out[(size_t)(r0 + 8)*VOCAB + c0] = v1;
        }
    }
}

/* ------------------ launch ------------------ */
extern "C" void kernel_launch(void* const* d_in, const int* in_sizes, int n_in,
                              void* d_out, int out_size) {
    const int*   idx  = (const int*)  d_in[0];
    const int*   src  = (const int*)  d_in[1];
    const int*   dst  = (const int*)  d_in[2];
    const float* Wemb = (const float*)d_in[3];
    const float* Gx   = (const float*)d_in[4];
    const float* Gy   = (const float*)d_in[5];
    const float* Gs   = (const float*)d_in[6];
    const float* Wout = (const float*)d_in[7];
    const float* bout = (const float*)d_in[8];
    float* out = (float*)d_out;

    long long btv = (long long)BB*TT*VOCAB;
    float* sig_out = ((long long)out_size >= btv + N_EDGES) ? (out + btv) : nullptr;

    static int smem_set = 0;
    if (!smem_set) {
        cudaFuncSetAttribute(k_gemm_mma, cudaFuncAttributeMaxDynamicSharedMemorySize, SMEM_GEMM);
        smem_set = 1;
    }

    k_hist   <<<512, 256>>>(dst);
    k_scan   <<<1, 1024>>>();
    k_scatter<<<512, 256>>>(dst);
    k_recurrent<<<RBLK, RTHR>>>(idx, Wemb, src, Gx, Gy, Gs, sig_out);  /* 4th: profiled */
    k_rstbar <<<1, 128>>>();
    k_convW  <<<(VOCAB*N_NEURONS/4 + 255)/256, 256>>>(Wout);
    k_transpose<<<(TT*N_NEURONS)/256, 256>>>();
    dim3 gg(BB*TT/128, VOCAB/128);
    k_gemm_mma<<<gg, 256, SMEM_GEMM>>>(bout, out);
}

// round 11
// speedup vs baseline: 2.2446x; 2.2446x over previous
#include <cuda_runtime.h>
#include <cuda_bf16.h>
#include <cstdint>

#define N_NEURONS 4096
#define N_EDGES   131072
#define VOCAB     8192
#define BB        8
#define TT        128
#define NB        (N_NEURONS*BB)
#define DECAYF    0.99f

#define RBLK   128
#define RTHR   512
#define NWARPS 16
#define NWARP  (RBLK*NWARPS)
#define NPW    2
#define CAP    2560
#define MAXB   128

/* ------------------ static device scratch ------------------ */
__device__ float g_Xall[TT*NB];                  /* (t,n,b) */
__device__ float g_xs  [TT*NB];
__device__ float g_S   [N_NEURONS*16];           /* x: +0..7, y: +8..15 */
__device__ float g_A[NB];
__device__ int   g_perm [N_EDGES];
__device__ int   g_counts[N_NEURONS];
__device__ int   g_cursor[N_NEURONS];
__device__ int   g_rowptr[N_NEURONS+1];
__device__ __nv_bfloat16 g_Ahi[BB*TT*N_NEURONS];
__device__ __nv_bfloat16 g_Alo[BB*TT*N_NEURONS];
__device__ __nv_bfloat16 g_Whi[VOCAB*N_NEURONS];
__device__ __nv_bfloat16 g_Wlo[VOCAB*N_NEURONS];

__device__ unsigned g_cnt = 0;
__device__ unsigned g_gen = 0;

__device__ __forceinline__ uint32_t smem_u32(const void* p) {
    uint32_t a;
    asm("{ .reg .u64 t; cvta.to.shared.u64 t, %1; cvt.u32.u64 %0, t; }" : "=r"(a) : "l"(p));
    return a;
}

/* ------------------ CSR preprocessing ------------------ */
__global__ void k_hist(const int* __restrict__ dst) {
    int e = blockIdx.x*blockDim.x + threadIdx.x;
    if (e < N_EDGES) atomicAdd(&g_counts[dst[e]], 1);
}
__global__ void k_scan() {
    __shared__ int sh[1024];
    int tid = threadIdx.x, base = tid*4;
    int v0 = g_counts[base+0], v1 = g_counts[base+1];
    int v2 = g_counts[base+2], v3 = g_counts[base+3];
    int s = v0+v1+v2+v3;
    sh[tid] = s; __syncthreads();
    for (int off = 1; off < 1024; off <<= 1) {
        int t = (tid >= off) ? sh[tid-off] : 0;
        __syncthreads(); sh[tid] += t; __syncthreads();
    }
    int excl = sh[tid] - s;
    g_rowptr[base+0] = excl; g_cursor[base+0] = excl; excl += v0;
    g_rowptr[base+1] = excl; g_cursor[base+1] = excl; excl += v1;
    g_rowptr[base+2] = excl; g_cursor[base+2] = excl; excl += v2;
    g_rowptr[base+3] = excl; g_cursor[base+3] = excl; excl += v3;
    if (tid == 1023) g_rowptr[N_NEURONS] = excl;
    g_counts[base+0]=0; g_counts[base+1]=0; g_counts[base+2]=0; g_counts[base+3]=0;
}
__global__ void k_scatter(const int* __restrict__ dst) {
    int e = blockIdx.x*blockDim.x + threadIdx.x;
    if (e < N_EDGES) { int p = atomicAdd(&g_cursor[dst[e]], 1); g_perm[p] = e; }
}

/* ------------------ W bf16 split ------------------ */
__global__ void k_convW(const float* __restrict__ W) {
    int i = blockIdx.x*blockDim.x + threadIdx.x;
    if (i >= VOCAB*N_NEURONS/4) return;
    float4 w = ((const float4*)W)[i];
    __nv_bfloat16 h[4], l[4];
    float v[4] = {w.x, w.y, w.z, w.w};
#pragma unroll
    for (int k = 0; k < 4; k++) {
        h[k] = __float2bfloat16_rn(v[k]);
        l[k] = __float2bfloat16_rn(v[k] - __bfloat162float(h[k]));
    }
    ((ushort4*)g_Whi)[i] = *(ushort4*)h;
    ((ushort4*)g_Wlo)[i] = *(ushort4*)l;
}

/* ------------------ grid barrier (R7: acq_rel counter + gen poll) ---------- */
__device__ __forceinline__ void gbar() {
    __syncthreads();
    if (threadIdx.x == 0) {
        unsigned* cntp = &g_cnt;
        unsigned* genp = &g_gen;
        unsigned gen, prev;
        asm volatile("ld.global.relaxed.gpu.u32 %0, [%1];" : "=r"(gen) : "l"(genp));
        asm volatile("atom.global.acq_rel.gpu.add.u32 %0, [%1], 1;"
                     : "=r"(prev) : "l"(cntp) : "memory");
        if (prev == (unsigned)(RBLK-1)) {
            unsigned z = 0, ng = gen + 1;
            asm volatile("st.global.relaxed.gpu.u32 [%0], %1;" :: "l"(cntp), "r"(z) : "memory");
            asm volatile("st.global.release.gpu.u32 [%0], %1;" :: "l"(genp), "r"(ng) : "memory");
        } else {
            unsigned v;
            do {
                asm volatile("ld.global.acquire.gpu.u32 %0, [%1];" : "=r"(v) : "l"(genp) : "memory");
            } while (v == gen);
        }
    }
    __syncthreads();
}

__device__ __forceinline__ void bfly4(float4& a) {
#pragma unroll
    for (int d = 2; d < 32; d <<= 1) {
        a.x += __shfl_xor_sync(0xffffffffu, a.x, d);
        a.y += __shfl_xor_sync(0xffffffffu, a.y, d);
        a.z += __shfl_xor_sync(0xffffffffu, a.z, d);
        a.w += __shfl_xor_sync(0xffffffffu, a.w, d);
    }
}

__global__ void __launch_bounds__(RTHR) k_recurrent(
        const int* __restrict__ idx, const float* __restrict__ Wemb,
        const int* __restrict__ srcA, const float* __restrict__ GxA,
        const float* __restrict__ GyA, const float* __restrict__ GsA,
        float* __restrict__ sig_out)
{
    __shared__ int   s_n[CAP];
    __shared__ float s_gs[CAP], s_gx[CAP], s_gy[CAP], s_sig[CAP];
    __shared__ int   s_wcnt[NWARPS], s_wbase[NWARPS+1];

    const int tid  = threadIdx.x;
    const int wid  = tid >> 5;
    const int lane = tid & 31;
    const int h    = lane & 1;                      /* batch half */
    const int es   = lane >> 1;                     /* edge slot */
    const int gtid = blockIdx.x*RTHR + tid;

    /* embed */
    for (int id = gtid; id < TT*N_NEURONS; id += RBLK*RTHR) {
        int t = id >> 12, n = id & (N_NEURONS-1);
        float v[8];
#pragma unroll
        for (int bb = 0; bb < 8; bb++)
            v[bb] = Wemb[(size_t)idx[bb*TT + t]*N_NEURONS + n];
        float4* o = (float4*)&g_Xall[(size_t)id*8];
        o[0] = make_float4(v[0], v[1], v[2], v[3]);
        o[1] = make_float4(v[4], v[5], v[6], v[7]);
    }

    /* this warp's 2 neurons; bins padded to multiples of 64 */
    int nrn[NPW], grs[NPW], cnt[NPW], pc[NPW], lb[NPW];
#pragma unroll
    for (int i = 0; i < NPW; i++) {
        nrn[i] = blockIdx.x*NWARPS*NPW + wid*NPW + i;
        grs[i] = g_rowptr[nrn[i]];
        cnt[i] = g_rowptr[nrn[i]+1] - grs[i];
        pc[i]  = (cnt[i] + 63) & ~63;
    }
    if (lane == 0) s_wcnt[wid] = pc[0] + pc[1];
    __syncthreads();
    if (tid == 0) {
        int acc = 0;
        for (int w = 0; w < NWARPS; w++) { s_wbase[w] = acc; acc += s_wcnt[w]; }
        s_wbase[NWARPS] = acc;
    }
    __syncthreads();
    lb[0] = s_wbase[wid];
    lb[1] = lb[0] + pc[0];

    if (lane < NPW) {
        int c = cnt[lane], g0 = grs[lane], l0 = lb[lane];
        int lbuf[MAXB];
        for (int j = 0; j < c; j++) lbuf[j] = g_perm[g0 + j];
        for (int i = 1; i < c; i++) {
            int key = lbuf[i], j = i-1;
            while (j >= 0 && lbuf[j] > key) { lbuf[j+1] = lbuf[j]; j--; }
            lbuf[j+1] = key;
        }
        for (int j = 0; j < c; j++) s_n[l0 + j] = lbuf[j];
    }
    __syncwarp();
#pragma unroll
    for (int i = 0; i < NPW; i++) {
        for (int j = lane; j < pc[i]; j += 32) {
            int pos = lb[i] + j;
            if (j < cnt[i]) {
                int e = s_n[pos];
                g_perm[grs[i] + j] = e;
                s_n[pos]  = e >= 0 ? srcA[e] : 0;
                s_gs[pos] = GsA[e];
                s_gx[pos] = GxA[e];
                s_gy[pos] = GyA[e];
            } else {
                s_n[pos] = 0; s_gs[pos] = 0.f; s_gx[pos] = 0.f; s_gy[pos] = 0.f;
            }
            s_sig[pos] = 0.0f;
        }
    }
    gbar();

    /* y0 = X[:,0,:] */
#pragma unroll
    for (int i = 0; i < NPW; i++)
        if (lane < 2)
            *(float4*)&g_S[nrn[i]*16 + 8 + h*4] = *(const float4*)&g_Xall[nrn[i]*8 + h*4];
    gbar();

    for (int t = 0; t < TT; t++) {
        const float* Xt = g_Xall + (size_t)t*NB;
        for (int layer = 0; layer < 2; layer++) {
            const float* xbase = (layer == 0) ? Xt : g_S;
            const int    xstr  = (layer == 0) ? 8 : 16;
            /* pass1: A[n] = sum x[src]*sigma(old) ; sigma hebbian update */
#pragma unroll
            for (int i = 0; i < NPW; i++) {
                float4 xn4 = *(const float4*)(xbase + (size_t)nrn[i]*xstr + h*4);
                float4 acc = make_float4(0.f, 0.f, 0.f, 0.f);
                for (int g = 0; g < pc[i]; g += 64) {
                    int base = lb[i] + g + es;
                    int ns[4]; float sg[4];
#pragma unroll
                    for (int u = 0; u < 4; u++) { ns[u] = s_n[base + u*16]; sg[u] = s_sig[base + u*16]; }
                    float4 xs[4], ys[4];
#pragma unroll
                    for (int u = 0; u < 4; u++) {
                        xs[u] = *(const float4*)(xbase + (size_t)ns[u]*xstr + h*4);
                        ys[u] = *(const float4*)(&g_S[ns[u]*16 + 8 + h*4]);
                    }
#pragma unroll
                    for (int u = 0; u < 4; u++) {
                        float p = ys[u].x*xn4.x + ys[u].y*xn4.y + ys[u].z*xn4.z + ys[u].w*xn4.w;
                        p += __shfl_xor_sync(0xffffffffu, p, 1);
                        acc.x += xs[u].x*sg[u]; acc.y += xs[u].y*sg[u];
                        acc.z += xs[u].z*sg[u]; acc.w += xs[u].w*sg[u];
                        if (h == 0)
                            s_sig[base + u*16] = fmaf(p*0.125f, s_gs[base + u*16], sg[u]) * DECAYF;
                    }
                }
                bfly4(acc);
                if (lane < 2) *(float4*)&g_A[nrn[i]*8 + h*4] = acc;
            }
            gbar();
            /* pass2: y[n] = sum relu(A[src])*Gy */
#pragma unroll
            for (int i = 0; i < NPW; i++) {
                float4 acc = make_float4(0.f, 0.f, 0.f, 0.f);
                for (int g = 0; g < pc[i]; g += 64) {
                    int base = lb[i] + g + es;
                    int ns[4]; float gy[4];
#pragma unroll
                    for (int u = 0; u < 4; u++) { ns[u] = s_n[base + u*16]; gy[u] = s_gy[base + u*16]; }
                    float4 a4[4];
#pragma unroll
                    for (int u = 0; u < 4; u++)
                        a4[u] = *(const float4*)(&g_A[ns[u]*8 + h*4]);
#pragma unroll
                    for (int u = 0; u < 4; u++) {
                        float ax = a4[u].x > 0.f ? a4[u].x : 0.f;
                        float ay = a4[u].y > 0.f ? a4[u].y : 0.f;
                        float az = a4[u].z > 0.f ? a4[u].z : 0.f;
                        float aw = a4[u].w > 0.f ? a4[u].w : 0.f;
                        acc.x += ax*gy[u]; acc.y += ay*gy[u];
                        acc.z += az*gy[u]; acc.w += aw*gy[u];
                    }
                }
                bfly4(acc);
                if (lane < 2) *(float4*)&g_S[nrn[i]*16 + 8 + h*4] = acc;
            }
            gbar();
            /* pass3: x[n] = relu(sum y[src]*Gx) */
#pragma unroll
            for (int i = 0; i < NPW; i++) {
                float4 acc = make_float4(0.f, 0.f, 0.f, 0.f);
                for (int g = 0; g < pc[i]; g += 64) {
                    int base = lb[i] + g + es;
                    int ns[4]; float gx[4];
#pragma unroll
                    for (int u = 0; u < 4; u++) { ns[u] = s_n[base + u*16]; gx[u] = s_gx[base + u*16]; }
                    float4 y4[4];
#pragma unroll
                    for (int u = 0; u < 4; u++)
                        y4[u] = *(const float4*)(&g_S[ns[u]*16 + 8 + h*4]);
#pragma unroll
                    for (int u = 0; u < 4; u++) {
                        acc.x += y4[u].x*gx[u]; acc.y += y4[u].y*gx[u];
                        acc.z += y4[u].z*gx[u]; acc.w += y4[u].w*gx[u];
                    }
                }
                bfly4(acc);
                if (lane < 2) {
                    acc.x = acc.x > 0.f ? acc.x : 0.f;  acc.y = acc.y > 0.f ? acc.y : 0.f;
                    acc.z = acc.z > 0.f ? acc.z : 0.f;  acc.w = acc.w > 0.f ? acc.w : 0.f;
                    if (layer == 0) *(float4*)&g_S[nrn[i]*16 + h*4] = acc;
                    else            *(float4*)&g_xs[(size_t)t*NB + nrn[i]*8 + h*4] = acc;
                }
            }
            /* layer-1 pass3 output only feeds the final GEMM -> skip barrier */
            if (layer == 0) gbar();
        }
    }

    if (sig_out)
#pragma unroll
        for (int i = 0; i < NPW; i++)
            for (int j = lane; j < cnt[i]; j += 32)
                sig_out[g_perm[grs[i] + j]] = s_sig[lb[i] + j];
}

/* ------------------ transpose + bf16 split of activations ------------------ */
__global__ void k_transpose() {
    int id = blockIdx.x*blockDim.x + threadIdx.x;
    if (id >= TT*N_NEURONS) return;
    int t = id >> 12, n = id & (N_NEURONS-1);
    const float4* p = (const float4*)&g_xs[(size_t)id*8];
    float4 v0 = p[0], v1 = p[1];
    float v[8] = {v0.x, v0.y, v0.z, v0.w, v1.x, v1.y, v1.z, v1.w};
#pragma unroll
    for (int bb = 0; bb < 8; bb++) {
        size_t o = (size_t)(bb*TT + t)*N_NEURONS + n;
        __nv_bfloat16 hh = __float2bfloat16_rn(v[bb]);
        g_Ahi[o] = hh;
        g_Alo[o] = __float2bfloat16_rn(v[bb] - __bfloat162float(hh));
    }
}

/* ------------------ mma.sync bf16 GEMM (split hi/lo, 3 segments) ----------- */
#define APITCH 40
#define STGB   (128*APITCH*2)
#define NSTG   3
#define SMEM_GEMM (2*NSTG*STGB)
#define NSTAGES_TOT 384

#define LDM4(r, a) asm volatile( \
    "ldmatrix.sync.aligned.m8n8.x4.shared.b16 {%0,%1,%2,%3}, [%4];" \
    : "=r"((r)[0]), "=r"((r)[1]), "=r"((r)[2]), "=r"((r)[3]) : "r"(a))

#define MMA16816(d, a, b0r, b1r) asm volatile( \
    "mma.sync.aligned.m16n8k16.row.col.f32.bf16.bf16.f32 " \
    "{%0,%1,%2,%3},{%4,%5,%6,%7},{%8,%9},{%0,%1,%2,%3};" \
    : "+f"((d)[0]), "+f"((d)[1]), "+f"((d)[2]), "+f"((d)[3]) \
    : "r"((a)[0]), "r"((a)[1]), "r"((a)[2]), "r"((a)[3]), "r"(b0r), "r"(b1r))

__global__ void __launch_bounds__(256) k_gemm_mma(const float* __restrict__ bias,
                                                  float* __restrict__ out)
{
    extern __shared__ char smem[];
    const uint32_t sA = smem_u32(smem);
    const uint32_t sB = sA + NSTG*STGB;
    const int tid  = threadIdx.x;
    const int wid  = tid >> 5;
    const int lane = tid & 31;
    const int wm = wid & 1, wn = wid >> 1;
    const int m0 = blockIdx.x * 128;
    const int n0 = blockIdx.y * 128;

    float acc[4][4][4];
#pragma unroll
    for (int i = 0; i < 4; i++)
#pragma unroll
        for (int j = 0; j < 4; j++)
#pragma unroll
            for (int k = 0; k < 4; k++) acc[i][j][k] = 0.0f;

    auto load_stage = [&](int gs, int slot) {
        int seg = gs >> 7;
        int k0  = (gs & 127) << 5;
        const __nv_bfloat16* Ap = (seg == 1) ? g_Alo : g_Ahi;
        const __nv_bfloat16* Bp = (seg == 2) ? g_Wlo : g_Whi;
#pragma unroll
        for (int i = tid; i < 512; i += 256) {
            int row = i >> 2, ch = i & 3;
            uint32_t da = sA + slot*STGB + (row*APITCH + ch*8)*2;
            const __nv_bfloat16* ga = Ap + (size_t)(m0 + row)*N_NEURONS + k0 + ch*8;
            asm volatile("cp.async.cg.shared.global [%0], [%1], 16;" :: "r"(da), "l"(ga) : "memory");
        }
#pragma unroll
        for (int i = tid; i < 512; i += 256) {
            int row = i >> 2, ch = i & 3;
            uint32_t db = sB + slot*STGB + (row*APITCH + ch*8)*2;
            const __nv_bfloat16* gb = Bp + (size_t)(n0 + row)*N_NEURONS + k0 + ch*8;
            asm volatile("cp.async.cg.shared.global [%0], [%1], 16;" :: "r"(db), "l"(gb) : "memory");
        }
        asm volatile("cp.async.commit_group;" ::: "memory");
    };

    load_stage(0, 0);
    load_stage(1, 1);

    for (int it = 0; it < NSTAGES_TOT; it++) {
        if (it + 2 < NSTAGES_TOT)
            asm volatile("cp.async.wait_group 1;" ::: "memory");
        else
            asm volatile("cp.async.wait_group 0;" ::: "memory");
        __syncthreads();
        if (it + 2 < NSTAGES_TOT)
            load_stage(it + 2, (it + 2) % NSTG);

        int slot = it % NSTG;
        uint32_t aB = sA + slot*STGB;
        uint32_t bB = sB + slot*STGB;
#pragma unroll
        for (int kk = 0; kk < 2; kk++) {
            uint32_t af[4][4], bf[2][4];
#pragma unroll
            for (int mi = 0; mi < 4; mi++) {
                uint32_t addr = aB + (uint32_t)(((wm*64 + mi*16 + (lane & 15))*APITCH
                                 + kk*16 + (lane >> 4)*8) * 2);
                LDM4(af[mi], addr);
            }
#pragma unroll
            for (int nh = 0; nh < 2; nh++) {
                int mat = lane >> 3;
                uint32_t addr = bB + (uint32_t)(((wn*32 + nh*16 + (lane & 7) + (mat >> 1)*8)*APITCH
                                 + kk*16 + (mat & 1)*8) * 2);
                LDM4(bf[nh], addr);
            }
#pragma unroll
            for (int mi = 0; mi < 4; mi++)
#pragma unroll
                for (int ni = 0; ni < 4; ni++)
                    MMA16816(acc[mi][ni], af[mi], bf[ni >> 1][(ni & 1)*2], bf[ni >> 1][(ni & 1)*2 + 1]);
        }
    }

    const int mb = m0 + wm*64;
    const int nb = n0 + wn*32;
#pragma unroll
    for (int ni = 0; ni < 4; ni++) {
        int c0 = nb + ni*8 + (lane & 3)*2;
        float bv0 = bias[c0], bv1 = bias[c0 + 1];
#pragma unroll
        for (int mi = 0; mi < 4; mi++) {
            int r0 = mb + mi*16 + (lane >> 2);
            float2 v0 = make_float2(acc[mi][ni][0] + bv0, acc[mi][ni][1] + bv1);
            float2 v1 = make_float2(acc[mi][ni][2] + bv0, acc[mi][ni][3] + bv1);
            *(float2*)&out[(size_t)r0*VOCAB + c0]       = v0;
            *(float2*)&out[(size_t)(r0 + 8)*VOCAB + c0] = v1;
        }
    }
}

/* ------------------ launch ------------------ */
extern "C" void kernel_launch(void* const* d_in, const int* in_sizes, int n_in,
                              void* d_out, int out_size) {
    const int*   idx  = (const int*)  d_in[0];
    const int*   src  = (const int*)  d_in[1];
    const int*   dst  = (const int*)  d_in[2];
    const float* Wemb = (const float*)d_in[3];
    const float* Gx   = (const float*)d_in[4];
    const float* Gy   = (const float*)d_in[5];
    const float* Gs   = (const float*)d_in[6];
    const float* Wout = (const float*)d_in[7];
    const float* bout = (const float*)d_in[8];
    float* out = (float*)d_out;

    long long btv = (long long)BB*TT*VOCAB;
    float* sig_out = ((long long)out_size >= btv + N_EDGES) ? (out + btv) : nullptr;

    static int smem_set = 0;
    if (!smem_set) {
        cudaFuncSetAttribute(k_gemm_mma, cudaFuncAttributeMaxDynamicSharedMemorySize, SMEM_GEMM);
        smem_set = 1;
    }

    k_hist   <<<512, 256>>>(dst);
    k_scan   <<<1, 1024>>>();
    k_scatter<<<512, 256>>>(dst);
    k_recurrent<<<RBLK, RTHR>>>(idx, Wemb, src, Gx, Gy, Gs, sig_out);  /* 4th: profiled */
    k_convW  <<<(VOCAB*N_NEURONS/4 + 255)/256, 256>>>(Wout);
    k_transpose<<<(TT*N_NEURONS)/256, 256>>>();
    dim3 gg(BB*TT/128, VOCAB/128);
    k_gemm_mma<<<gg, 256, SMEM_GEMM>>>(bout, out);
}

// round 12
// speedup vs baseline: 2.3908x; 1.0651x over previous
#include <cuda_runtime.h>
#include <cuda_bf16.h>
#include <cstdint>

#define N_NEURONS 4096
#define N_EDGES   131072
#define VOCAB     8192
#define BB        8
#define TT        128
#define NB        (N_NEURONS*BB)
#define DECAYF    0.99f

#define RBLK   128
#define RTHR   1024
#define NWARPS 32
#define CAP    2048
#define MAXB   128

/* ------------------ static device scratch ------------------ */
__device__ float g_Xall[TT*NB];                  /* (t,n,b) */
__device__ float g_xs  [TT*NB];
__device__ float g_S   [N_NEURONS*16];           /* x: +0..7, y: +8..15 */
__device__ float g_A[NB];
__device__ int   g_perm [N_EDGES];
__device__ int   g_counts[N_NEURONS];
__device__ int   g_cursor[N_NEURONS];
__device__ int   g_rowptr[N_NEURONS+1];
__device__ __nv_bfloat16 g_Ahi[BB*TT*N_NEURONS];
__device__ __nv_bfloat16 g_Alo[BB*TT*N_NEURONS];
__device__ __nv_bfloat16 g_Whi[VOCAB*N_NEURONS];
__device__ __nv_bfloat16 g_Wlo[VOCAB*N_NEURONS];

__device__ unsigned g_cnt = 0;
__device__ unsigned g_gen = 0;

__device__ __forceinline__ uint32_t smem_u32(const void* p) {
    uint32_t a;
    asm("{ .reg .u64 t; cvta.to.shared.u64 t, %1; cvt.u32.u64 %0, t; }" : "=r"(a) : "l"(p));
    return a;
}

/* ------------------ CSR preprocessing ------------------ */
__global__ void k_hist(const int* __restrict__ dst) {
    int e = blockIdx.x*blockDim.x + threadIdx.x;
    if (e < N_EDGES) atomicAdd(&g_counts[dst[e]], 1);
}
__global__ void k_scan() {
    __shared__ int sh[1024];
    int tid = threadIdx.x, base = tid*4;
    int v0 = g_counts[base+0], v1 = g_counts[base+1];
    int v2 = g_counts[base+2], v3 = g_counts[base+3];
    int s = v0+v1+v2+v3;
    sh[tid] = s; __syncthreads();
    for (int off = 1; off < 1024; off <<= 1) {
        int t = (tid >= off) ? sh[tid-off] : 0;
        __syncthreads(); sh[tid] += t; __syncthreads();
    }
    int excl = sh[tid] - s;
    g_rowptr[base+0] = excl; g_cursor[base+0] = excl; excl += v0;
    g_rowptr[base+1] = excl; g_cursor[base+1] = excl; excl += v1;
    g_rowptr[base+2] = excl; g_cursor[base+2] = excl; excl += v2;
    g_rowptr[base+3] = excl; g_cursor[base+3] = excl; excl += v3;
    if (tid == 1023) g_rowptr[N_NEURONS] = excl;
    g_counts[base+0]=0; g_counts[base+1]=0; g_counts[base+2]=0; g_counts[base+3]=0;
}
__global__ void k_scatter(const int* __restrict__ dst) {
    int e = blockIdx.x*blockDim.x + threadIdx.x;
    if (e < N_EDGES) { int p = atomicAdd(&g_cursor[dst[e]], 1); g_perm[p] = e; }
}

/* ------------------ W bf16 split ------------------ */
__global__ void k_convW(const float* __restrict__ W) {
    int i = blockIdx.x*blockDim.x + threadIdx.x;
    if (i >= VOCAB*N_NEURONS/4) return;
    float4 w = ((const float4*)W)[i];
    __nv_bfloat16 h[4], l[4];
    float v[4] = {w.x, w.y, w.z, w.w};
#pragma unroll
    for (int k = 0; k < 4; k++) {
        h[k] = __float2bfloat16_rn(v[k]);
        l[k] = __float2bfloat16_rn(v[k] - __bfloat162float(h[k]));
    }
    ((ushort4*)g_Whi)[i] = *(ushort4*)h;
    ((ushort4*)g_Wlo)[i] = *(ushort4*)l;
}

/* ------------------ grid barrier (R7: acq_rel counter + gen poll) ---------- */
__device__ __forceinline__ void gbar() {
    __syncthreads();
    if (threadIdx.x == 0) {
        unsigned* cntp = &g_cnt;
        unsigned* genp = &g_gen;
        unsigned gen, prev;
        asm volatile("ld.global.relaxed.gpu.u32 %0, [%1];" : "=r"(gen) : "l"(genp));
        asm volatile("atom.global.acq_rel.gpu.add.u32 %0, [%1], 1;"
                     : "=r"(prev) : "l"(cntp) : "memory");
        if (prev == (unsigned)(RBLK-1)) {
            unsigned z = 0, ng = gen + 1;
            asm volatile("st.global.relaxed.gpu.u32 [%0], %1;" :: "l"(cntp), "r"(z) : "memory");
            asm volatile("st.global.release.gpu.u32 [%0], %1;" :: "l"(genp), "r"(ng) : "memory");
        } else {
            unsigned v;
            do {
                asm volatile("ld.global.acquire.gpu.u32 %0, [%1];" : "=r"(v) : "l"(genp) : "memory");
            } while (v == gen);
        }
    }
    __syncthreads();
}

__device__ __forceinline__ void bfly4(float4& a) {
#pragma unroll
    for (int d = 2; d < 32; d <<= 1) {
        a.x += __shfl_xor_sync(0xffffffffu, a.x, d);
        a.y += __shfl_xor_sync(0xffffffffu, a.y, d);
        a.z += __shfl_xor_sync(0xffffffffu, a.z, d);
        a.w += __shfl_xor_sync(0xffffffffu, a.w, d);
    }
}

__global__ void __launch_bounds__(RTHR) k_recurrent(
        const int* __restrict__ idx, const float* __restrict__ Wemb,
        const int* __restrict__ srcA, const float* __restrict__ GxA,
        const float* __restrict__ GyA, const float* __restrict__ GsA,
        float* __restrict__ sig_out)
{
    __shared__ int   s_n[CAP];
    __shared__ float s_gs[CAP], s_gx[CAP], s_gy[CAP], s_sig[CAP];
    __shared__ int   s_wcnt[NWARPS], s_wbase[NWARPS+1];

    const int tid  = threadIdx.x;
    const int wid  = tid >> 5;
    const int lane = tid & 31;
    const int nrn  = blockIdx.x*NWARPS + wid;       /* 1 neuron per warp */
    const int h    = lane & 1;                      /* batch half */
    const int es   = lane >> 1;                     /* edge slot */
    const int gtid = blockIdx.x*RTHR + tid;

    /* embed */
    for (int id = gtid; id < TT*N_NEURONS; id += RBLK*RTHR) {
        int t = id >> 12, n = id & (N_NEURONS-1);
        float v[8];
#pragma unroll
        for (int bb = 0; bb < 8; bb++)
            v[bb] = Wemb[(size_t)idx[bb*TT + t]*N_NEURONS + n];
        float4* o = (float4*)&g_Xall[(size_t)id*8];
        o[0] = make_float4(v[0], v[1], v[2], v[3]);
        o[1] = make_float4(v[4], v[5], v[6], v[7]);
    }

    /* stage edges (padded to 32 per neuron) */
    const int grs = g_rowptr[nrn];
    const int cnt = g_rowptr[nrn+1] - grs;
    const int pc  = (cnt + 31) & ~31;
    if (lane == 0) s_wcnt[wid] = pc;
    __syncthreads();
    if (tid == 0) {
        int acc = 0;
        for (int w = 0; w < NWARPS; w++) { s_wbase[w] = acc; acc += s_wcnt[w]; }
        s_wbase[NWARPS] = acc;
    }
    __syncthreads();
    const int lb = s_wbase[wid];

    if (lane == 0) {
        int lbuf[MAXB];
        for (int j = 0; j < cnt; j++) lbuf[j] = g_perm[grs + j];
        for (int i = 1; i < cnt; i++) {
            int key = lbuf[i], j = i-1;
            while (j >= 0 && lbuf[j] > key) { lbuf[j+1] = lbuf[j]; j--; }
            lbuf[j+1] = key;
        }
        for (int j = 0; j < cnt; j++) s_n[lb + j] = lbuf[j];
    }
    __syncwarp();
    for (int j = lane; j < pc; j += 32) {
        int pos = lb + j;
        if (j < cnt) {
            int e = s_n[pos];
            g_perm[grs + j] = e;
            s_n[pos]  = srcA[e];
            s_gs[pos] = GsA[e];
            s_gx[pos] = GxA[e];
            s_gy[pos] = GyA[e];
        } else {
            s_n[pos] = 0; s_gs[pos] = 0.f; s_gx[pos] = 0.f; s_gy[pos] = 0.f;
        }
        s_sig[pos] = 0.0f;
    }
    gbar();

    /* y0 = X[:,0,:] */
    if (lane < 2)
        *(float4*)&g_S[nrn*16 + 8 + h*4] = *(const float4*)&g_Xall[nrn*8 + h*4];
    gbar();

    for (int t = 0; t < TT; t++) {
        const float* Xt = g_Xall + (size_t)t*NB;
        for (int layer = 0; layer < 2; layer++) {
            const float* xbase = (layer == 0) ? Xt : g_S;
            const int    xstr  = (layer == 0) ? 8 : 16;
            /* pass1: A[n] = sum x[src]*sigma(old) ; sigma hebbian update */
            {
                float4 xn4 = *(const float4*)(xbase + (size_t)nrn*xstr + h*4);
                float4 acc = make_float4(0.f, 0.f, 0.f, 0.f);
                for (int j0 = 0; j0 < pc; j0 += 16) {
                    int   slot = lb + j0 + es;
                    int   ns   = s_n[slot];
                    float sg   = s_sig[slot];
                    float4 xs4 = *(const float4*)(xbase + (size_t)ns*xstr + h*4);
                    float4 ys4 = *(const float4*)(&g_S[ns*16 + 8 + h*4]);
                    float p = ys4.x*xn4.x + ys4.y*xn4.y + ys4.z*xn4.z + ys4.w*xn4.w;
                    p += __shfl_xor_sync(0xffffffffu, p, 1);
                    acc.x += xs4.x*sg; acc.y += xs4.y*sg;
                    acc.z += xs4.z*sg; acc.w += xs4.w*sg;
                    if (h == 0)
                        s_sig[slot] = fmaf(p*0.125f, s_gs[slot], sg) * DECAYF;
                }
                bfly4(acc);
                if (lane < 2) *(float4*)&g_A[nrn*8 + h*4] = acc;
            }
            gbar();
            /* pass2: y[n] = sum relu(A[src])*Gy */
            {
                float4 acc = make_float4(0.f, 0.f, 0.f, 0.f);
                for (int j0 = 0; j0 < pc; j0 += 16) {
                    int   slot = lb + j0 + es;
                    int   ns   = s_n[slot];
                    float gy   = s_gy[slot];
                    float4 a4  = *(const float4*)(&g_A[ns*8 + h*4]);
                    a4.x = a4.x > 0.f ? a4.x : 0.f;  a4.y = a4.y > 0.f ? a4.y : 0.f;
                    a4.z = a4.z > 0.f ? a4.z : 0.f;  a4.w = a4.w > 0.f ? a4.w : 0.f;
                    acc.x += a4.x*gy; acc.y += a4.y*gy;
                    acc.z += a4.z*gy; acc.w += a4.w*gy;
                }
                bfly4(acc);
                if (lane < 2) *(float4*)&g_S[nrn*16 + 8 + h*4] = acc;
            }
            gbar();
            /* pass3: x[n] = relu(sum y[src]*Gx) */
            {
                float4 acc = make_float4(0.f, 0.f, 0.f, 0.f);
                for (int j0 = 0; j0 < pc; j0 += 16) {
                    int   slot = lb + j0 + es;
                    int   ns   = s_n[slot];
                    float gx   = s_gx[slot];
                    float4 y4  = *(const float4*)(&g_S[ns*16 + 8 + h*4]);
                    acc.x += y4.x*gx; acc.y += y4.y*gx;
                    acc.z += y4.z*gx; acc.w += y4.w*gx;
                }
                bfly4(acc);
                if (lane < 2) {
                    acc.x = acc.x > 0.f ? acc.x : 0.f;  acc.y = acc.y > 0.f ? acc.y : 0.f;
                    acc.z = acc.z > 0.f ? acc.z : 0.f;  acc.w = acc.w > 0.f ? acc.w : 0.f;
                    if (layer == 0) *(float4*)&g_S[nrn*16 + h*4] = acc;
                    else            *(float4*)&g_xs[(size_t)t*NB + nrn*8 + h*4] = acc;
                }
            }
            if (layer == 0) gbar();
        }
    }

    if (sig_out)
        for (int j = lane; j < cnt; j += 32)
            sig_out[g_perm[grs + j]] = s_sig[lb + j];
}

/* ------------------ transpose + bf16 split of activations ------------------ */
__global__ void k_transpose() {
    int id = blockIdx.x*blockDim.x + threadIdx.x;
    if (id >= TT*N_NEURONS) return;
    int t = id >> 12, n = id & (N_NEURONS-1);
    const float4* p = (const float4*)&g_xs[(size_t)id*8];
    float4 v0 = p[0], v1 = p[1];
    float v[8] = {v0.x, v0.y, v0.z, v0.w, v1.x, v1.y, v1.z, v1.w};
#pragma unroll
    for (int bb = 0; bb < 8; bb++) {
        size_t o = (size_t)(bb*TT + t)*N_NEURONS + n;
        __nv_bfloat16 hh = __float2bfloat16_rn(v[bb]);
        g_Ahi[o] = hh;
        g_Alo[o] = __float2bfloat16_rn(v[bb] - __bfloat162float(hh));
    }
}

/* ------------------ mma.sync bf16 GEMM: 128x256 tile, warp 64x64 ----------- */
#define APITCH 40
#define ASTGB  (128*APITCH*2)            /* 10240 B */
#define BSTGB  (256*APITCH*2)            /* 20480 B */
#define NSTG   3
#define SMEM_GEMM (NSTG*(ASTGB + BSTGB)) /* 92160 B */
#define NSTAGES_TOT 384

#define LDM4(r, a) asm volatile( \
    "ldmatrix.sync.aligned.m8n8.x4.shared.b16 {%0,%1,%2,%3}, [%4];" \
    : "=r"((r)[0]), "=r"((r)[1]), "=r"((r)[2]), "=r"((r)[3]) : "r"(a))

#define MMA16816(d, a, b0r, b1r) asm volatile( \
    "mma.sync.aligned.m16n8k16.row.col.f32.bf16.bf16.f32 " \
    "{%0,%1,%2,%3},{%4,%5,%6,%7},{%8,%9},{%0,%1,%2,%3};" \
    : "+f"((d)[0]), "+f"((d)[1]), "+f"((d)[2]), "+f"((d)[3]) \
    : "r"((a)[0]), "r"((a)[1]), "r"((a)[2]), "r"((a)[3]), "r"(b0r), "r"(b1r))

__global__ void __launch_bounds__(256, 1) k_gemm_mma(const float* __restrict__ bias,
                                                     float* __restrict__ out)
{
    extern __shared__ char smem[];
    const uint32_t sA = smem_u32(smem);
    const uint32_t sB = sA + NSTG*ASTGB;
    const int tid  = threadIdx.x;
    const int wid  = tid >> 5;
    const int lane = tid & 31;
    const int wm = wid & 1, wn = wid >> 1;   /* warp grid 2(M) x 4(N), tile 64x64 */
    const int m0 = blockIdx.x * 128;
    const int n0 = blockIdx.y * 256;

    float acc[4][8][4];
#pragma unroll
    for (int i = 0; i < 4; i++)
#pragma unroll
        for (int j = 0; j < 8; j++)
#pragma unroll
            for (int k = 0; k < 4; k++) acc[i][j][k] = 0.0f;

    auto load_stage = [&](int gs, int slot) {
        int seg = gs >> 7;
        int k0  = (gs & 127) << 5;
        const __nv_bfloat16* Ap = (seg == 1) ? g_Alo : g_Ahi;
        const __nv_bfloat16* Bp = (seg == 2) ? g_Wlo : g_Whi;
#pragma unroll
        for (int i = tid; i < 1536; i += 256) {
            if (i < 512) {
                int row = i >> 2, ch = i & 3;
                uint32_t da = sA + slot*ASTGB + (row*APITCH + ch*8)*2;
                const __nv_bfloat16* ga = Ap + (size_t)(m0 + row)*N_NEURONS + k0 + ch*8;
                asm volatile("cp.async.cg.shared.global [%0], [%1], 16;" :: "r"(da), "l"(ga) : "memory");
            } else {
                int i2 = i - 512;
                int row = i2 >> 2, ch = i2 & 3;
                uint32_t db = sB + slot*BSTGB + (row*APITCH + ch*8)*2;
                const __nv_bfloat16* gb = Bp + (size_t)(n0 + row)*N_NEURONS + k0 + ch*8;
                asm volatile("cp.async.cg.shared.global [%0], [%1], 16;" :: "r"(db), "l"(gb) : "memory");
            }
        }
        asm volatile("cp.async.commit_group;" ::: "memory");
    };

    load_stage(0, 0);
    load_stage(1, 1);

    for (int it = 0; it < NSTAGES_TOT; it++) {
        if (it + 2 < NSTAGES_TOT)
            asm volatile("cp.async.wait_group 1;" ::: "memory");
        else
            asm volatile("cp.async.wait_group 0;" ::: "memory");
        __syncthreads();
        if (it + 2 < NSTAGES_TOT)
            load_stage(it + 2, (it + 2) % NSTG);

        int slot = it % NSTG;
        uint32_t aB = sA + slot*ASTGB;
        uint32_t bB = sB + slot*BSTGB;
#pragma unroll
        for (int kk = 0; kk < 2; kk++) {
            uint32_t af[4][4], bf[4][4];
#pragma unroll
            for (int mi = 0; mi < 4; mi++) {
                uint32_t addr = aB + (uint32_t)(((wm*64 + mi*16 + (lane & 15))*APITCH
                                 + kk*16 + (lane >> 4)*8) * 2);
                LDM4(af[mi], addr);
            }
#pragma unroll
            for (int nh = 0; nh < 4; nh++) {
                int mat = lane >> 3;
                uint32_t addr = bB + (uint32_t)(((wn*64 + nh*16 + (lane & 7) + (mat >> 1)*8)*APITCH
                                 + kk*16 + (mat & 1)*8) * 2);
                LDM4(bf[nh], addr);
            }
#pragma unroll
            for (int mi = 0; mi < 4; mi++)
#pragma unroll
                for (int ni = 0; ni < 8; ni++)
                    MMA16816(acc[mi][ni], af[mi], bf[ni >> 1][(ni & 1)*2], bf[ni >> 1][(ni & 1)*2 + 1]);
        }
    }

    const int mb = m0 + wm*64;
    const int nb = n0 + wn*64;
#pragma unroll
    for (int ni = 0; ni < 8; ni++) {
        int c0 = nb + ni*8 + (lane & 3)*2;
        float bv0 = bias[c0], bv1 = bias[c0 + 1];
#pragma unroll
        for (int mi = 0; mi < 4; mi++) {
            int r0 = mb + mi*16 + (lane >> 2);
            float2 v0 = make_float2(acc[mi][ni][0] + bv0, acc[mi][ni][1] + bv1);
            float2 v1 = make_float2(acc[mi][ni][2] + bv0, acc[mi][ni][3] + bv1);
            *(float2*)&out[(size_t)r0*VOCAB + c0]       = v0;
            *(float2*)&out[(size_t)(r0 + 8)*VOCAB + c0] = v1;
        }
    }
}

/* ------------------ launch ------------------ */
extern "C" void kernel_launch(void* const* d_in, const int* in_sizes, int n_in,
                              void* d_out, int out_size) {
    const int*   idx  = (const int*)  d_in[0];
    const int*   src  = (const int*)  d_in[1];
    const int*   dst  = (const int*)  d_in[2];
    const float* Wemb = (const float*)d_in[3];
    const float* Gx   = (const float*)d_in[4];
    const float* Gy   = (const float*)d_in[5];
    const float* Gs   = (const float*)d_in[6];
    const float* Wout = (const float*)d_in[7];
    const float* bout = (const float*)d_in[8];
    float* out = (float*)d_out;

    long long btv = (long long)BB*TT*VOCAB;
    float* sig_out = ((long long)out_size >= btv + N_EDGES) ? (out + btv) : nullptr;

    static int smem_set = 0;
    if (!smem_set) {
        cudaFuncSetAttribute(k_gemm_mma, cudaFuncAttributeMaxDynamicSharedMemorySize, SMEM_GEMM);
        smem_set = 1;
    }

    k_hist   <<<512, 256>>>(dst);
    k_scan   <<<1, 1024>>>();
    k_scatter<<<512, 256>>>(dst);
    k_recurrent<<<RBLK, RTHR>>>(idx, Wemb, src, Gx, Gy, Gs, sig_out);  /* 4th: profiled */
    k_convW  <<<(VOCAB*N_NEURONS/4 + 255)/256, 256>>>(Wout);
    k_transpose<<<(TT*N_NEURONS)/256, 256>>>();
    dim3 gg(BB*TT/128, VOCAB/256);
    k_gemm_mma<<<gg, 256, SMEM_GEMM>>>(bout, out);
}